// round 12
// baseline (speedup 1.0000x reference)
#include <cuda_runtime.h>
#include <cstdint>
#include <float.h>

#define B_ 128
#define H_ 14
#define W_ 14
#define C_ 512
#define C2_ (C_ / 2)
#define C4_ (C_ / 4)
#define HW_ (H_ * W_)
#define ITERS_ 10
#define NCHUNK 14
#define CHUNKLEN 14

#define NCTA 296           // 2 CTAs/SM x 148 SMs: all co-resident (spin-safe)
#define TPB 512
#define DELAY 24           // C lags A by 24 batches in dispatch order
#define EARLY (7 * DELAY)                 // 168 A-only works
#define MIXED ((B_ - DELAY) * 14)         // 1456 interleaved works
#define TOTAL_WORKS (EARLY + MIXED + 7 * DELAY)  // 1792 = 896 A + 896 C
#define BN4 (HW_ * C4_)    // 25088 float4 per batch
#define SEGN4 (7 * TPB)    // 3584 float4 per C work (7 iters)

// Scratch (device globals: no allocs allowed)
__device__ float2 g_pbest2[B_ * NCHUNK * C2_];
__device__ unsigned short g_pidx2[B_ * NCHUNK * C2_];
__device__ unsigned int g_assign_words[B_ * C4_];
__device__ int g_sync[257];   // [0]=work counter, [1..128]=cnt, [129..256]=flag

__global__ void zero_sync_kernel() {
    if (threadIdx.x < 257) g_sync[threadIdx.x] = 0;
}

// ---------------------------------------------------------------------------
// Inline k-means for batch b (512 threads). Identical math to the proven
// kernel B (bit-exact integer-grid arithmetic).
// ---------------------------------------------------------------------------
__device__ __forceinline__ void run_kmeans(int b, int t, int* hist,
                                           float* sinit, float* scent)
{
    const int c = t;
    if (c < HW_) hist[c] = 0;

    const float* pbest = (const float*)g_pbest2;
    const unsigned char* pidx = (const unsigned char*)g_pidx2;

    float best = -FLT_MAX;
    int bestIdx = 0;
#pragma unroll
    for (int k = 0; k < NCHUNK; k++) {
        const int o = (b * NCHUNK + k) * C_ + c;
        const float v = pbest[o];
        if (v > best) { best = v; bestIdx = k * CHUNKLEN + (int)pidx[o]; }
    }
    const float px = (float)(bestIdx % W_);
    const float py = (float)(bestIdx / W_);

    if (c == 0) { sinit[0] = px; sinit[1] = py; }
    if (c == 1) { sinit[2] = px; sinit[3] = py; }
    __syncthreads();

    atomicAdd(&hist[bestIdx], 1);
    __syncthreads();

    if (c < 32) {
        int cnt[7]; float bx[7], by[7];
        int sx = 0, sy = 0;
#pragma unroll
        for (int j = 0; j < 7; j++) {
            const int bin = c * 7 + j;
            const int n = (bin < HW_) ? hist[bin] : 0;
            cnt[j] = n;
            bx[j] = (float)(bin % W_);
            by[j] = (float)(bin / W_);
            sx += n * (bin % W_);
            sy += n * (bin / W_);
        }
        const int Sx = __reduce_add_sync(0xffffffffu, sx);
        const int Sy = __reduce_add_sync(0xffffffffu, sy);

        float c0x = sinit[0], c0y = sinit[1];
        float c1x = sinit[2], c1y = sinit[3];

        for (int it = 0; it < ITERS_; it++) {
            int s1x = 0, s1y = 0, n1 = 0;
#pragma unroll
            for (int j = 0; j < 7; j++) {
                const float dx0 = bx[j] - c0x, dy0 = by[j] - c0y;
                const float dx1 = bx[j] - c1x, dy1 = by[j] - c1y;
                const float d0 = dx0 * dx0 + dy0 * dy0;
                const float d1 = dx1 * dx1 + dy1 * dy1;
                const int m = (d1 < d0) ? cnt[j] : 0;
                n1 += m;
                s1x += m * (int)bx[j];
                s1y += m * (int)by[j];
            }
            const int T1x = __reduce_add_sync(0xffffffffu, s1x);
            const int T1y = __reduce_add_sync(0xffffffffu, s1y);
            const int T1n = __reduce_add_sync(0xffffffffu, n1);

            const float inv1 = 1.0f / fmaxf((float)T1n, 1.0f);
            const float inv0 = 1.0f / fmaxf((float)(C_ - T1n), 1.0f);
            // reference swaps clusters each update
            c0x = (float)T1x * inv1; c0y = (float)T1y * inv1;
            c1x = (float)(Sx - T1x) * inv0; c1y = (float)(Sy - T1y) * inv0;
        }
        if (c == 0) { scent[0] = c0x; scent[1] = c0y; scent[2] = c1x; scent[3] = c1y; }
    }
    __syncthreads();

    const float dx0 = px - scent[0], dy0 = py - scent[1];
    const float dx1 = px - scent[2], dy1 = py - scent[3];
    const int assign = ((dx1 * dx1 + dy1 * dy1) < (dx0 * dx0 + dy0 * dy0)) ? 1 : 0;
    ((unsigned char*)g_assign_words)[b * C_ + c] = (unsigned char)assign;
}

// ---------------------------------------------------------------------------
// Persistent pipeline kernel: atomic work queue interleaving A-reads and
// C-writes so the HBM read and write streams overlap.
// ---------------------------------------------------------------------------
__global__ __launch_bounds__(TPB, 2) void pipeline_kernel(
    const float2* __restrict__ in2, const float4* __restrict__ in4,
    float4* __restrict__ out0, float4* __restrict__ out1)
{
    __shared__ int s_g, s_doB;
    __shared__ int hist[HW_];
    __shared__ float sinit[4], scent[4];

    const int t = threadIdx.x;

    for (;;) {
        if (t == 0) s_g = atomicAdd(&g_sync[0], 1);
        __syncthreads();
        const int g = s_g;
        if (g >= TOTAL_WORKS) return;

        int b = 0, pair = 0, cb = 0, seg = 0;
        bool isA;
        if (g < EARLY) {
            isA = true; b = g / 7; pair = g % 7;
        } else if (g < EARLY + MIXED) {
            const int h = g - EARLY;
            const int q = h / 14, r = h % 14;
            if (r < 7) { isA = true; b = DELAY + q; pair = r; }
            else       { isA = false; cb = q; seg = r - 7; }
        } else {
            const int h = g - EARLY - MIXED;
            isA = false; cb = (B_ - DELAY) + h / 7; seg = h % 7;
        }

        if (isA) {
            // ---- A work: 2 chunks, float2 per thread ----
            const int chunk = 2 * pair + (t >> 8);
            const int hh = t & (C2_ / 2 - 1) & 255;  // t & 255
            const float2* base =
                in2 + ((size_t)b * HW_ + chunk * CHUNKLEN) * C2_ + (t & 255);
            float b0 = -FLT_MAX, b1 = -FLT_MAX;
            int i0 = 0, i1 = 0;
#pragma unroll
            for (int i = 0; i < CHUNKLEN; i++) {
                const float2 v = __ldg(base + (size_t)i * C2_);
                if (v.x > b0) { b0 = v.x; i0 = i; }
                if (v.y > b1) { b1 = v.y; i1 = i; }
            }
            const int o = (b * NCHUNK + chunk) * C2_ + (t & 255);
            g_pbest2[o] = make_float2(b0, b1);
            g_pidx2[o] = (unsigned short)(i0 | (i1 << 8));
            (void)hh;
            __syncthreads();
            if (t == 0) {
                __threadfence();  // release partials before count
                const int old = atomicAdd(&g_sync[1 + b], 1);
                s_doB = (old == 6);  // last arriver runs k-means
            }
            __syncthreads();
            if (s_doB) {
                __threadfence();  // acquire all 14 chunk partials
                run_kmeans(b, t, hist, sinit, scent);
                __syncthreads();
                if (t == 0) {
                    __threadfence();  // release assignments before flag
                    atomicExch(&g_sync[129 + b], 1);
                }
            }
            __syncthreads();
        } else {
            // ---- C work: 7 mask iterations for 1/7 of batch cb ----
            if (t == 0) {
                while (atomicAdd(&g_sync[129 + cb], 0) == 0) __nanosleep(64);
                __threadfence();  // acquire assignments
            }
            __syncthreads();

            const unsigned int am = g_assign_words[cb * C4_ + (t & (C4_ - 1))];
            const bool m0 = (am & 0x000000ffu) != 0;
            const bool m1 = (am & 0x0000ff00u) != 0;
            const bool m2 = (am & 0x00ff0000u) != 0;
            const bool m3 = (am & 0xff000000u) != 0;

            const int ibase = cb * BN4 + seg * SEGN4 + t;
#pragma unroll
            for (int k = 0; k < 7; k++) {
                const int i = ibase + k * TPB;
                const float4 x = __ldg(in4 + i);
                float4 z0, z1;
                z1.x = m0 ? x.x : 0.f;  z0.x = m0 ? 0.f : x.x;
                z1.y = m1 ? x.y : 0.f;  z0.y = m1 ? 0.f : x.y;
                z1.z = m2 ? x.z : 0.f;  z0.z = m2 ? 0.f : x.z;
                z1.w = m3 ? x.w : 0.f;  z0.w = m3 ? 0.f : x.w;
                __stcs(out0 + i, z0);
                __stcs(out1 + i, z1);
            }
            __syncthreads();  // protect s_g reuse
        }
    }
}

extern "C" void kernel_launch(void* const* d_in, const int* in_sizes, int n_in,
                              void* d_out, int out_size)
{
    const float* in = (const float*)d_in[0];
    float* out = (float*)d_out;
    const int n_elem = B_ * HW_ * C_;  // 12,845,056

    zero_sync_kernel<<<1, 288>>>();
    pipeline_kernel<<<NCTA, TPB>>>((const float2*)in, (const float4*)in,
                                   (float4*)out, (float4*)(out + n_elem));
}

// round 13
// speedup vs baseline: 1.3344x; 1.3344x over previous
#include <cuda_runtime.h>
#include <cstdint>
#include <float.h>

#define B_ 128
#define H_ 14
#define W_ 14
#define C_ 512
#define C4_ (C_ / 4)
#define C8_ (C_ / 8)
#define HW_ (H_ * W_)
#define ITERS_ 10
#define NCHUNK 14
#define CHUNKLEN 14   // 196 / 14

// Scratch (device globals: no allocs allowed)
__device__ float4 g_pbest4[B_ * NCHUNK * C4_];
__device__ unsigned int g_pidx4[B_ * NCHUNK * C4_];
__device__ unsigned long long g_assign8[B_ * C8_];   // 8 assign bytes per entry

__device__ __forceinline__ unsigned long long keep_policy() {
    unsigned long long policy;
    asm("createpolicy.fractional.L2::evict_last.b64 %0, 1.0;" : "=l"(policy));
    return policy;
}

__device__ __forceinline__ float4 ldg_keep(const float4* p,
                                           unsigned long long policy) {
    float4 v;
    asm("ld.global.nc.L2::cache_hint.v4.f32 {%0,%1,%2,%3}, [%4], %5;"
        : "=f"(v.x), "=f"(v.y), "=f"(v.z), "=f"(v.w)
        : "l"(p), "l"(policy));
    return v;
}

// ---------------------------------------------------------------------------
// Kernel A: partial spatial argmax, float4-wide (R11 form, best measured
// 11.4us). grid (B, NCHUNK) = 1792 x 128. Thread = one channel-quad.
// ---------------------------------------------------------------------------
__global__ __launch_bounds__(C4_) void argmax_partial_kernel(
    const float4* __restrict__ in4)
{
    const int b = blockIdx.x;
    const int chunk = blockIdx.y;
    const int q = threadIdx.x;
    const unsigned long long pol = keep_policy();

    const float4* base = in4 + ((size_t)b * HW_ + chunk * CHUNKLEN) * C4_ + q;
    float bx = -FLT_MAX, by = -FLT_MAX, bz = -FLT_MAX, bw = -FLT_MAX;
    int ix = 0, iy = 0, iz = 0, iw = 0;
#pragma unroll
    for (int i = 0; i < CHUNKLEN; i++) {
        const float4 v = ldg_keep(base + (size_t)i * C4_, pol);
        if (v.x > bx) { bx = v.x; ix = i; }
        if (v.y > by) { by = v.y; iy = i; }
        if (v.z > bz) { bz = v.z; iz = i; }
        if (v.w > bw) { bw = v.w; iw = i; }
    }
    const int o = (b * NCHUNK + chunk) * C4_ + q;
    g_pbest4[o] = make_float4(bx, by, bz, bw);
    g_pidx4[o] = (unsigned int)ix | ((unsigned int)iy << 8) |
                 ((unsigned int)iz << 16) | ((unsigned int)iw << 24);
}

// ---------------------------------------------------------------------------
// Kernel B: combine partials; 196-bin histogram; warp-0 k-means (REDUX);
// classify. grid = B, 512 threads. (unchanged, bit-exact)
// ---------------------------------------------------------------------------
__global__ __launch_bounds__(C_, 1) void kmeans_kernel()
{
    const int b = blockIdx.x;
    const int c = threadIdx.x;

    __shared__ int hist[HW_];
    __shared__ float sinit[4];
    __shared__ float scent[4];

    if (c < HW_) hist[c] = 0;

    const float* pbest = (const float*)g_pbest4;
    const unsigned char* pidx = (const unsigned char*)g_pidx4;

    float best = -FLT_MAX;
    int bestIdx = 0;
#pragma unroll
    for (int k = 0; k < NCHUNK; k++) {
        const int o = (b * NCHUNK + k) * C_ + c;
        const float v = pbest[o];
        if (v > best) { best = v; bestIdx = k * CHUNKLEN + (int)pidx[o]; }
    }
    const float px = (float)(bestIdx % W_);
    const float py = (float)(bestIdx / W_);

    if (c == 0) { sinit[0] = px; sinit[1] = py; }
    if (c == 1) { sinit[2] = px; sinit[3] = py; }
    __syncthreads();

    atomicAdd(&hist[bestIdx], 1);
    __syncthreads();

    if (c < 32) {
        int cnt[7]; float bx[7], by[7];
        int sx = 0, sy = 0;
#pragma unroll
        for (int j = 0; j < 7; j++) {
            const int bin = c * 7 + j;
            const int n = (bin < HW_) ? hist[bin] : 0;
            cnt[j] = n;
            bx[j] = (float)(bin % W_);
            by[j] = (float)(bin / W_);
            sx += n * (bin % W_);
            sy += n * (bin / W_);
        }
        const int Sx = __reduce_add_sync(0xffffffffu, sx);
        const int Sy = __reduce_add_sync(0xffffffffu, sy);

        float c0x = sinit[0], c0y = sinit[1];
        float c1x = sinit[2], c1y = sinit[3];

        for (int it = 0; it < ITERS_; it++) {
            int s1x = 0, s1y = 0, n1 = 0;
#pragma unroll
            for (int j = 0; j < 7; j++) {
                const float dx0 = bx[j] - c0x, dy0 = by[j] - c0y;
                const float dx1 = bx[j] - c1x, dy1 = by[j] - c1y;
                const float d0 = dx0 * dx0 + dy0 * dy0;
                const float d1 = dx1 * dx1 + dy1 * dy1;
                const int m = (d1 < d0) ? cnt[j] : 0;
                n1 += m;
                s1x += m * (int)bx[j];
                s1y += m * (int)by[j];
            }
            const int T1x = __reduce_add_sync(0xffffffffu, s1x);
            const int T1y = __reduce_add_sync(0xffffffffu, s1y);
            const int T1n = __reduce_add_sync(0xffffffffu, n1);

            const float inv1 = 1.0f / fmaxf((float)T1n, 1.0f);
            const float inv0 = 1.0f / fmaxf((float)(C_ - T1n), 1.0f);
            // reference swaps clusters each update
            c0x = (float)T1x * inv1; c0y = (float)T1y * inv1;
            c1x = (float)(Sx - T1x) * inv0; c1y = (float)(Sy - T1y) * inv0;
        }
        if (c == 0) { scent[0] = c0x; scent[1] = c0y; scent[2] = c1x; scent[3] = c1y; }
    }
    __syncthreads();

    const float dx0 = px - scent[0], dy0 = py - scent[1];
    const float dx1 = px - scent[2], dy1 = py - scent[3];
    const int assign = ((dx1 * dx1 + dy1 * dy1) < (dx0 * dx0 + dy0 * dy0)) ? 1 : 0;
    ((unsigned char*)g_assign8)[b * C_ + c] = (unsigned char)assign;
}

// ---------------------------------------------------------------------------
// Kernel C: mask split with 256-bit ops. Thread = 8 consecutive channels:
// one v8.b32 load (evict_last), two v8.b32 streaming (.cs) stores.
// Selection on raw u32 bits (bit-exact). Halves LSU/L1 wavefront pressure.
// ---------------------------------------------------------------------------
__global__ __launch_bounds__(256) void mask_kernel_v8(
    const float* __restrict__ in, float* __restrict__ out0,
    float* __restrict__ out1)
{
    const int i = blockIdx.x * blockDim.x + threadIdx.x;  // unit = 8 floats

    const int c8 = i & (C8_ - 1);
    const int b = i / (C8_ * HW_);
    const unsigned long long am = g_assign8[b * C8_ + c8];

    const float* p = in + (size_t)i * 8;
    unsigned int x[8];
    asm("ld.global.nc.L2::evict_last.v8.b32 {%0,%1,%2,%3,%4,%5,%6,%7}, [%8];"
        : "=r"(x[0]), "=r"(x[1]), "=r"(x[2]), "=r"(x[3]),
          "=r"(x[4]), "=r"(x[5]), "=r"(x[6]), "=r"(x[7])
        : "l"(p));

    unsigned int z0[8], z1[8];
#pragma unroll
    for (int j = 0; j < 8; j++) {
        const bool m = ((am >> (8 * j)) & 0xffull) != 0;
        z1[j] = m ? x[j] : 0u;
        z0[j] = m ? 0u : x[j];
    }

    asm volatile(
        "st.global.cs.v8.b32 [%0], {%1,%2,%3,%4,%5,%6,%7,%8};"
        :: "l"(out0 + (size_t)i * 8),
           "r"(z0[0]), "r"(z0[1]), "r"(z0[2]), "r"(z0[3]),
           "r"(z0[4]), "r"(z0[5]), "r"(z0[6]), "r"(z0[7]) : "memory");
    asm volatile(
        "st.global.cs.v8.b32 [%0], {%1,%2,%3,%4,%5,%6,%7,%8};"
        :: "l"(out1 + (size_t)i * 8),
           "r"(z1[0]), "r"(z1[1]), "r"(z1[2]), "r"(z1[3]),
           "r"(z1[4]), "r"(z1[5]), "r"(z1[6]), "r"(z1[7]) : "memory");
}

extern "C" void kernel_launch(void* const* d_in, const int* in_sizes, int n_in,
                              void* d_out, int out_size)
{
    const float* in = (const float*)d_in[0];
    float* out = (float*)d_out;
    const int n_elem = B_ * HW_ * C_;  // 12,845,056

    argmax_partial_kernel<<<dim3(B_, NCHUNK), C4_>>>((const float4*)in);
    kmeans_kernel<<<B_, C_>>>();

    const int n8 = n_elem / 8;  // 1,605,632 = 6272 * 256 exactly
    mask_kernel_v8<<<n8 / 256, 256>>>(in, out, out + n_elem);
}

// round 14
// speedup vs baseline: 1.4591x; 1.0934x over previous
#include <cuda_runtime.h>
#include <cstdint>
#include <float.h>

#define B_ 128
#define H_ 14
#define W_ 14
#define C_ 512
#define C4_ (C_ / 4)
#define HW_ (H_ * W_)
#define ITERS_ 10
#define NCHUNK 14
#define CHUNKLEN 14   // 196 / 14

// Scratch (device globals: no allocs allowed)
__device__ float4 g_pbest4[B_ * NCHUNK * C4_];
__device__ unsigned int g_pidx4[B_ * NCHUNK * C4_];
__device__ unsigned int g_assign_words[(B_ * C_) / 4];

// L2 evict_last via createpolicy + cache_hint (kernel A only — measured win
// there; measured ~1us loss when used in the 12544-block mask kernel).
__device__ __forceinline__ unsigned long long keep_policy() {
    unsigned long long policy;
    asm("createpolicy.fractional.L2::evict_last.b64 %0, 1.0;" : "=l"(policy));
    return policy;
}

__device__ __forceinline__ float4 ldg_keep(const float4* p,
                                           unsigned long long policy) {
    float4 v;
    asm("ld.global.nc.L2::cache_hint.v4.f32 {%0,%1,%2,%3}, [%4], %5;"
        : "=f"(v.x), "=f"(v.y), "=f"(v.z), "=f"(v.w)
        : "l"(p), "l"(policy));
    return v;
}

// ---------------------------------------------------------------------------
// Kernel A: partial spatial argmax, float4-wide, evict_last loads.
// grid (B, NCHUNK) = 1792 x 128. Thread = one channel-quad. (R11 form, 11.4us)
// ---------------------------------------------------------------------------
__global__ __launch_bounds__(C4_) void argmax_partial_kernel(
    const float4* __restrict__ in4)
{
    const int b = blockIdx.x;
    const int chunk = blockIdx.y;
    const int q = threadIdx.x;
    const unsigned long long pol = keep_policy();

    const float4* base = in4 + ((size_t)b * HW_ + chunk * CHUNKLEN) * C4_ + q;
    float bx = -FLT_MAX, by = -FLT_MAX, bz = -FLT_MAX, bw = -FLT_MAX;
    int ix = 0, iy = 0, iz = 0, iw = 0;
#pragma unroll
    for (int i = 0; i < CHUNKLEN; i++) {
        const float4 v = ldg_keep(base + (size_t)i * C4_, pol);
        if (v.x > bx) { bx = v.x; ix = i; }
        if (v.y > by) { by = v.y; iy = i; }
        if (v.z > bz) { bz = v.z; iz = i; }
        if (v.w > bw) { bw = v.w; iw = i; }
    }
    const int o = (b * NCHUNK + chunk) * C4_ + q;
    g_pbest4[o] = make_float4(bx, by, bz, bw);
    g_pidx4[o] = (unsigned int)ix | ((unsigned int)iy << 8) |
                 ((unsigned int)iz << 16) | ((unsigned int)iw << 24);
}

// ---------------------------------------------------------------------------
// Kernel B: combine partials; 196-bin histogram; warp-0 k-means (REDUX);
// classify. grid = B, 512 threads. (bit-exact vs reference)
// ---------------------------------------------------------------------------
__global__ __launch_bounds__(C_, 1) void kmeans_kernel()
{
    const int b = blockIdx.x;
    const int c = threadIdx.x;

    __shared__ int hist[HW_];
    __shared__ float sinit[4];
    __shared__ float scent[4];

    if (c < HW_) hist[c] = 0;

    const float* pbest = (const float*)g_pbest4;
    const unsigned char* pidx = (const unsigned char*)g_pidx4;

    // ascending chunk scan with strict '>' keeps first occurrence
    float best = -FLT_MAX;
    int bestIdx = 0;
#pragma unroll
    for (int k = 0; k < NCHUNK; k++) {
        const int o = (b * NCHUNK + k) * C_ + c;
        const float v = pbest[o];
        if (v > best) { best = v; bestIdx = k * CHUNKLEN + (int)pidx[o]; }
    }
    const float px = (float)(bestIdx % W_);
    const float py = (float)(bestIdx / W_);

    if (c == 0) { sinit[0] = px; sinit[1] = py; }
    if (c == 1) { sinit[2] = px; sinit[3] = py; }
    __syncthreads();

    atomicAdd(&hist[bestIdx], 1);
    __syncthreads();

    if (c < 32) {
        int cnt[7]; float bx[7], by[7];
        int sx = 0, sy = 0;
#pragma unroll
        for (int j = 0; j < 7; j++) {
            const int bin = c * 7 + j;
            const int n = (bin < HW_) ? hist[bin] : 0;
            cnt[j] = n;
            bx[j] = (float)(bin % W_);
            by[j] = (float)(bin / W_);
            sx += n * (bin % W_);
            sy += n * (bin / W_);
        }
        const int Sx = __reduce_add_sync(0xffffffffu, sx);
        const int Sy = __reduce_add_sync(0xffffffffu, sy);

        float c0x = sinit[0], c0y = sinit[1];
        float c1x = sinit[2], c1y = sinit[3];

        for (int it = 0; it < ITERS_; it++) {
            int s1x = 0, s1y = 0, n1 = 0;
#pragma unroll
            for (int j = 0; j < 7; j++) {
                const float dx0 = bx[j] - c0x, dy0 = by[j] - c0y;
                const float dx1 = bx[j] - c1x, dy1 = by[j] - c1y;
                const float d0 = dx0 * dx0 + dy0 * dy0;
                const float d1 = dx1 * dx1 + dy1 * dy1;
                const int m = (d1 < d0) ? cnt[j] : 0;
                n1 += m;
                s1x += m * (int)bx[j];
                s1y += m * (int)by[j];
            }
            const int T1x = __reduce_add_sync(0xffffffffu, s1x);
            const int T1y = __reduce_add_sync(0xffffffffu, s1y);
            const int T1n = __reduce_add_sync(0xffffffffu, n1);

            const float inv1 = 1.0f / fmaxf((float)T1n, 1.0f);
            const float inv0 = 1.0f / fmaxf((float)(C_ - T1n), 1.0f);
            // reference swaps clusters each update
            c0x = (float)T1x * inv1; c0y = (float)T1y * inv1;
            c1x = (float)(Sx - T1x) * inv0; c1y = (float)(Sy - T1y) * inv0;
        }
        if (c == 0) { scent[0] = c0x; scent[1] = c0y; scent[2] = c1x; scent[3] = c1y; }
    }
    __syncthreads();

    const float dx0 = px - scent[0], dy0 = py - scent[1];
    const float dx1 = px - scent[2], dy1 = py - scent[3];
    const int assign = ((dx1 * dx1 + dy1 * dy1) < (dx0 * dx0 + dy0 * dy0)) ? 1 : 0;
    ((unsigned char*)g_assign_words)[b * C_ + c] = (unsigned char)assign;
}

// ---------------------------------------------------------------------------
// Kernel C: streaming mask split — EXACT round-2 form (best measured).
// Plain __ldg float4 + __stcs streaming stores, 1 float4 per thread.
// ---------------------------------------------------------------------------
__global__ __launch_bounds__(256) void mask_kernel(
    const float4* __restrict__ in, float4* __restrict__ out0,
    float4* __restrict__ out1)
{
    const int i = blockIdx.x * blockDim.x + threadIdx.x;  // grid covers n4 exactly

    const int c4 = i & (C4_ - 1);
    const int b = i / (C4_ * HW_);

    const unsigned int am = g_assign_words[b * C4_ + c4];
    const float4 x = __ldg(in + i);

    float4 z0, z1;
    const bool m0 = (am & 0x000000ffu) != 0;
    const bool m1 = (am & 0x0000ff00u) != 0;
    const bool m2 = (am & 0x00ff0000u) != 0;
    const bool m3 = (am & 0xff000000u) != 0;
    z1.x = m0 ? x.x : 0.f;  z0.x = m0 ? 0.f : x.x;
    z1.y = m1 ? x.y : 0.f;  z0.y = m1 ? 0.f : x.y;
    z1.z = m2 ? x.z : 0.f;  z0.z = m2 ? 0.f : x.z;
    z1.w = m3 ? x.w : 0.f;  z0.w = m3 ? 0.f : x.w;

    __stcs(out0 + i, z0);
    __stcs(out1 + i, z1);
}

extern "C" void kernel_launch(void* const* d_in, const int* in_sizes, int n_in,
                              void* d_out, int out_size)
{
    const float* in = (const float*)d_in[0];
    float* out = (float*)d_out;
    const int n_elem = B_ * HW_ * C_;  // 12,845,056

    argmax_partial_kernel<<<dim3(B_, NCHUNK), C4_>>>((const float4*)in);
    kmeans_kernel<<<B_, C_>>>();

    const int n4 = n_elem / 4;  // 3,211,264 = 12544 * 256 exactly
    mask_kernel<<<n4 / 256, 256>>>((const float4*)in, (float4*)out,
                                   (float4*)(out + n_elem));
}